// round 11
// baseline (speedup 1.0000x reference)
#include <cuda_runtime.h>
#include <cuda_bf16.h>

// Problem shapes (fixed by the dataset)
constexpr int Bsz = 4096;   // batch rows
constexpr int Lh  = 128;    // sequence length
constexpr int Dd  = 64;     // feature dim
constexpr int Vv  = 1000;   // vocab size (id range)
constexpr int NC  = 129;    // possible count values 0..128

// LUT: f(c)[d] = sum_e relu(c*W1[e]+b1[e]) * W2[e][d]
__device__ float g_lut[NC * Dd];

__global__ void lut_kernel(const float* __restrict__ W1,
                           const float* __restrict__ b1,
                           const float* __restrict__ W2) {
    const int c = blockIdx.x;   // count value 0..128
    const int d = threadIdx.x;  // output dim 0..63
    __shared__ float h[Dd];
    h[d] = fmaxf(fmaf((float)c, W1[d], b1[d]), 0.0f);
    __syncthreads();
    float acc = 0.0f;
#pragma unroll
    for (int e = 0; e < Dd; e++)
        acc = fmaf(h[e], W2[e * Dd + d], acc);
    g_lut[c * Dd + d] = acc;
}

// One block per batch row. 256 threads:
//   threads [0,128)   handle src positions, [128,256) handle dst positions.
// Phase 1: per-row id histograms (src list, dst list) in shared.
// Phase 2: counts via histogram lookup; fold into weighted count-histogram hw.
// Phase 3: compact nonzero hw entries (typically ~3-6).
// Phase 4: out[side][b][d] = (sum_c hw[c]*lut[c][d]) * (e-1) + 2*b2[d].
__global__ __launch_bounds__(256, 8) void pool_kernel(
    const int* __restrict__ src_ids, const int* __restrict__ dst_ids,
    const float* __restrict__ b2, float* __restrict__ out)
{
    __shared__ int   s_hist[2][Vv];   // id histograms: [0]=src list, [1]=dst list
    __shared__ float s_hw[2][NC];     // weighted count histogram per side
    __shared__ int   s_nz[2][NC];     // compacted nonzero count values
    __shared__ int   s_nnz[2];

    const int b    = blockIdx.x;
    const int t    = threadIdx.x;
    const int side = t >> 7;          // 0 = src positions, 1 = dst positions
    const int i    = t & 127;         // position within sequence

    // ---- clear shared state ----
    for (int k = t; k < 2 * Vv; k += 256) (&s_hist[0][0])[k] = 0;
    for (int k = t; k < 2 * NC; k += 256) (&s_hw[0][0])[k]   = 0.0f;
    if (t < 2) s_nnz[t] = 0;

    // each thread owns one (side, position) id
    const int* ids = side ? dst_ids : src_ids;
    const int  id  = ids[b * Lh + i];
    __syncthreads();

    // ---- phase 1: histograms over both id lists ----
    atomicAdd(&s_hist[side][id], 1);
    __syncthreads();

    // ---- phase 2: counts + weighted count-histogram ----
    // channel order in reference: [x_in_src, x_in_dst]; channels are summed,
    // so both feed the same hw[side].
    int c1 = 0, c2 = 0;
    if (id != 0) {                    // padding (id==0) -> counts forced to 0
        c1 = s_hist[0][id];           // appearances in src list
        c2 = s_hist[1][id];           // appearances in dst list
    }
    const float w = __expf((float)(i - Lh));   // exp(k - L); underflows to 0 like ref
    atomicAdd(&s_hw[side][c1], w);
    atomicAdd(&s_hw[side][c2], w);
    __syncthreads();

    // ---- phase 3: compact nonzero hw entries ----
    for (int k = t; k < 2 * NC; k += 256) {
        float v = (&s_hw[0][0])[k];
        if (v != 0.0f) {
            int sd = (k >= NC) ? 1 : 0;
            int p  = atomicAdd(&s_nnz[sd], 1);
            s_nz[sd][p] = sd ? (k - NC) : k;
        }
    }
    __syncthreads();

    // ---- phase 4: sparse LUT contraction + epilogue ----
    if (t < 2 * Dd) {
        const int sd = t >> 6;        // output side
        const int d  = t & (Dd - 1);
        const int nnz = s_nnz[sd];
        float acc = 0.0f;
        for (int m = 0; m < nnz; m++) {
            int c = s_nz[sd][m];
            acc = fmaf(s_hw[sd][c], g_lut[c * Dd + d], acc);
        }
        // 1 / w.sum() = (e - 1) / (1 - e^-128)  ~=  e - 1  (corr ~2.6e-56)
        out[sd * (Bsz * Dd) + b * Dd + d] =
            acc * 1.7182818284590452f + 2.0f * b2[d];
    }
}

extern "C" void kernel_launch(void* const* d_in, const int* in_sizes, int n_in,
                              void* d_out, int out_size) {
    const int*   src = (const int*)d_in[0];
    const int*   dst = (const int*)d_in[1];
    const float* W1  = (const float*)d_in[2];
    const float* b1  = (const float*)d_in[3];
    const float* W2  = (const float*)d_in[4];
    const float* b2  = (const float*)d_in[5];
    float* out = (float*)d_out;

    lut_kernel<<<NC, Dd>>>(W1, b1, W2);
    pool_kernel<<<Bsz, 256>>>(src, dst, b2, out);
}

// round 12
// speedup vs baseline: 1.7694x; 1.7694x over previous
#include <cuda_runtime.h>
#include <cuda_bf16.h>

// Problem shapes (fixed by the dataset)
constexpr int Bsz = 4096;   // batch rows
constexpr int Lh  = 128;    // sequence length
constexpr int Dd  = 64;     // feature dim
constexpr int Vv  = 1000;   // vocab size (id range)
constexpr int NC  = 129;    // possible count values 0..128
constexpr int TAIL = 32;    // positions with numerically relevant weight
                            // (e^{i-128} < 1.3e-14 relative for i < 96)

// LUT: f(c)[d] = sum_e relu(c*W1[e]+b1[e]) * W2[e][d]
__device__ float g_lut[NC * Dd];

__global__ void lut_kernel(const float* __restrict__ W1,
                           const float* __restrict__ b1,
                           const float* __restrict__ W2) {
    const int c = blockIdx.x;   // count value 0..128
    const int d = threadIdx.x;  // output dim 0..63
    __shared__ float h[Dd];
    h[d] = fmaxf(fmaf((float)c, W1[d], b1[d]), 0.0f);
    __syncthreads();
    float acc = 0.0f;
#pragma unroll
    for (int e = 0; e < Dd; e++)
        acc = fmaf(h[e], W2[e * Dd + d], acc);
    g_lut[c * Dd + d] = acc;
}

// One block per batch row, 256 threads:
//   thread t owns (side = t>>7, position i = t&127); side 0 = src, 1 = dst.
// Phase 1: per-row id histograms for both lists (all 128 positions).
// Phase 2: ONLY the tail 32 positions per side (warps 3 and 7) fold their
//          exp-weights into the weighted count-histogram hw; the first
//          toucher of each hw[c] registers c in the nz-list (no scan pass).
// Phase 3: out[side][b][d] = (sum_nz hw[c]*lut[c][d]) * (e-1) + 2*b2[d].
__global__ __launch_bounds__(256, 8) void pool_kernel(
    const int* __restrict__ src_ids, const int* __restrict__ dst_ids,
    const float* __restrict__ b2, float* __restrict__ out)
{
    __shared__ alignas(16) int s_hist[2 * Vv];  // [0:Vv)=src list, [Vv:2Vv)=dst
    __shared__ float s_hw[2][NC];               // weighted count histogram
    __shared__ int   s_nz[2][2 * TAIL];         // distinct counts touched
    __shared__ int   s_nnz[2];

    const int b    = blockIdx.x;
    const int t    = threadIdx.x;
    const int side = t >> 7;
    const int i    = t & 127;

    // ---- clear shared state (vectorized) ----
    int4* h4 = reinterpret_cast<int4*>(s_hist);
#pragma unroll
    for (int k = t; k < (2 * Vv) / 4; k += 256)
        h4[k] = make_int4(0, 0, 0, 0);
    if (t < 2 * NC) (&s_hw[0][0])[t] = 0.0f;
    if (t < 2)      { s_nnz[t] = 0; (&s_hw[0][0])[256 + t] = 0.0f; }

    // each thread owns one (side, position) id
    const int* ids = side ? dst_ids : src_ids;
    const int  id  = ids[b * Lh + i];
    __syncthreads();

    // ---- phase 1: histograms over both full id lists ----
    atomicAdd(&s_hist[side * Vv + id], 1);
    __syncthreads();

    // ---- phase 2: tail positions only -> weighted count histogram ----
    if (i >= Lh - TAIL) {                       // warps 3 and 7 exactly
        int c1 = 0, c2 = 0;
        if (id != 0) {                          // padding forces counts to 0
            c1 = s_hist[id];                    // appearances in src list
            c2 = s_hist[Vv + id];               // appearances in dst list
        }
        const float w = __expf((float)(i - Lh));
        float o1 = atomicAdd(&s_hw[side][c1], w);
        if (o1 == 0.0f) { int p = atomicAdd(&s_nnz[side], 1); s_nz[side][p] = c1; }
        float o2 = atomicAdd(&s_hw[side][c2], w);
        if (o2 == 0.0f) { int p = atomicAdd(&s_nnz[side], 1); s_nz[side][p] = c2; }
    }
    __syncthreads();

    // ---- phase 3: sparse LUT contraction + epilogue ----
    if (t < 2 * Dd) {
        const int sd  = t >> 6;
        const int d   = t & (Dd - 1);
        const int nnz = s_nnz[sd];
        float acc = 0.0f;
        for (int m = 0; m < nnz; m++) {
            int c = s_nz[sd][m];                // broadcast LDS (same per side)
            acc = fmaf(s_hw[sd][c], g_lut[c * Dd + d], acc);
        }
        // 1 / w.sum() = (e-1)/(1 - e^-128) ~= e - 1
        out[sd * (Bsz * Dd) + b * Dd + d] =
            acc * 1.7182818284590452f + 2.0f * b2[d];
    }
}

extern "C" void kernel_launch(void* const* d_in, const int* in_sizes, int n_in,
                              void* d_out, int out_size) {
    const int*   src = (const int*)d_in[0];
    const int*   dst = (const int*)d_in[1];
    const float* W1  = (const float*)d_in[2];
    const float* b1  = (const float*)d_in[3];
    const float* W2  = (const float*)d_in[4];
    const float* b2  = (const float*)d_in[5];
    float* out = (float*)d_out;

    lut_kernel<<<NC, Dd>>>(W1, b1, W2);
    pool_kernel<<<Bsz, 256>>>(src, dst, b2, out);
}